// round 13
// baseline (speedup 1.0000x reference)
#include <cuda_runtime.h>
#include <cuda_bf16.h>
#include <math.h>
#include <stdint.h>

// Problem constants
#define Bb   64
#define NPG  400
#define Kk   250
#define Ff   64
#define LIN  16000
#define Hh   8000
#define Nn   (Bb*NPG)        // 25600
#define BN_EPS 1e-5f

#define KSPLIT 8             // 7 chunks of 2048 + 1 of 1664
#define NCTA1  (63 * KSPLIT) // 504

// Scratch (device globals; no allocation allowed)
__device__ __nv_bfloat16 g_xb[Bb*LIN];      // bf16 normalized features
__device__ int   g_selidx[Bb*Kk];
__device__ float g_stanh[Bb*Kk];
__device__ float g_hpart[KSPLIT][Bb][Hh];   // split-K partials
__device__ float g_lm[Bb];                  // per-m logit accumulators
__device__ int   g_jcnt[63];                // per-jblock completion counters
__device__ int   g_done;                    // global completion counter

// ---------------------------------------------------------------------------
// Kernel: fused scores + bitonic top-K; writes selected idx + tanh(score)
// Block 0 also zeroes g_lm for this launch (stream-ordered before gemm1).
// ---------------------------------------------------------------------------
__global__ void k_sort(const float* __restrict__ feat, const float* __restrict__ w) {
    __shared__ float sv[512];
    __shared__ int   si[512];
    __shared__ float s_inv;
    int tid = threadIdx.x, b = blockIdx.x;
    int warp = tid >> 5, lane = tid & 31;

    if (b == 0 && tid < Bb) g_lm[tid] = 0.f;

    if (tid == 0) {
        float s = 0.f;
        #pragma unroll
        for (int i = 0; i < Ff; i++) s += w[i] * w[i];
        s_inv = rsqrtf(s);
    }
    const float* xg = feat + (size_t)11 * Nn * Ff + (size_t)b * NPG * Ff;
    float wl0 = w[lane], wl1 = w[lane + 32];
    for (int nd = warp; nd < NPG; nd += 16) {
        const float* x = xg + (size_t)nd * Ff;
        float v = x[lane] * wl0 + x[lane + 32] * wl1;
        #pragma unroll
        for (int o = 16; o > 0; o >>= 1) v += __shfl_down_sync(0xffffffffu, v, o);
        if (lane == 0) sv[nd] = v;
    }
    if (tid >= NPG) sv[tid] = __int_as_float(0xff800000);
    si[tid] = tid;
    __syncthreads();

    // Bitonic sort: value descending, index ascending on ties
    for (int k = 2; k <= 512; k <<= 1) {
        for (int j = k >> 1; j > 0; j >>= 1) {
            int ixj = tid ^ j;
            if (ixj > tid) {
                float va = sv[tid], vb = sv[ixj];
                int   ia = si[tid], ib = si[ixj];
                bool aFirst = (va > vb) || (va == vb && ia < ib);
                bool bFirst = (vb > va) || (vb == va && ib < ia);
                bool desc = ((tid & k) == 0);
                bool sw = desc ? bFirst : aFirst;
                if (sw) { sv[tid] = vb; sv[ixj] = va; si[tid] = ib; si[ixj] = ia; }
            }
            __syncthreads();
        }
    }
    if (tid < Kk) {
        g_selidx[b * Kk + tid] = si[tid];
        g_stanh[b * Kk + tid]  = tanhf(sv[tid] * s_inv);
    }
}

// ---------------------------------------------------------------------------
// Kernel: gather + BatchNorm -> bf16 xn   grid (64, 8)
// ---------------------------------------------------------------------------
__global__ void k_bn(const float* __restrict__ feat,
                     const float* __restrict__ bn_mean, const float* __restrict__ bn_var,
                     const float* __restrict__ bn_gamma, const float* __restrict__ bn_beta) {
    int b = blockIdx.x, q = blockIdx.y, tid = threadIdx.x;
    const float* xg = feat + (size_t)11 * Nn * Ff + (size_t)b * NPG * Ff;
    int base = q * (LIN / 8);
    for (int t = tid; t < LIN / 8; t += 256) {
        int i = base + t;
        int r = i >> 6, f = i & 63;
        int idx = g_selidx[b * Kk + r];
        float st = g_stanh[b * Kk + r];
        float xv = xg[idx * Ff + f];
        float xn = (xv * st - bn_mean[i]) * rsqrtf(bn_var[i] + BN_EPS) * bn_gamma[i] + bn_beta[i];
        g_xb[(size_t)b * LIN + i] = __float2bfloat16(xn);
    }
}

// ---------------------------------------------------------------------------
// GEMM1 + fused split-reduce + loss.
// Mainloop (frozen R12 structure): 128 thr (4 warps), warp tile 32m x 64j,
// BN=128, BK=32, 2-stage smem, 4 CTAs/SM. W: LDG->bf16->STS. X: cp.async.
// Tail: per-jblock finisher reduces hpart (L2-hot) -> relu -> x W2 -> g_lm;
// global-last CTA computes BCE loss.
// ---------------------------------------------------------------------------
#define BN1   128
#define BK1   32
#define ROWB  80                    // bytes per smem row (40 halves)
#define W_BYTES (128 * ROWB)        // 10240
#define X_BYTES (64 * ROWB)         // 5120
#define STG_B   (W_BYTES + X_BYTES) // 15360

__device__ __forceinline__ void mma16816(float* d,
                                         unsigned a0, unsigned a1, unsigned a2, unsigned a3,
                                         unsigned b0, unsigned b1) {
    asm volatile(
        "mma.sync.aligned.m16n8k16.row.col.f32.bf16.bf16.f32 "
        "{%0,%1,%2,%3}, {%4,%5,%6,%7}, {%8,%9}, {%0,%1,%2,%3};\n"
        : "+f"(d[0]), "+f"(d[1]), "+f"(d[2]), "+f"(d[3])
        : "r"(a0), "r"(a1), "r"(a2), "r"(a3), "r"(b0), "r"(b1));
}

__device__ __forceinline__ void ldsm4(unsigned& r0, unsigned& r1, unsigned& r2, unsigned& r3,
                                      unsigned addr) {
    asm volatile("ldmatrix.sync.aligned.m8n8.x4.shared.b16 {%0,%1,%2,%3}, [%4];"
                 : "=r"(r0), "=r"(r1), "=r"(r2), "=r"(r3) : "r"(addr));
}

__device__ __forceinline__ void cpa16(unsigned dst, const void* src) {
    asm volatile("cp.async.cg.shared.global [%0], [%1], 16;" :: "r"(dst), "l"(src));
}

__global__ __launch_bounds__(128, 4) void k_gemm1(const float* __restrict__ W1,
                                                  const float* __restrict__ b1,
                                                  const float* __restrict__ W2,
                                                  const float* __restrict__ b2,
                                                  float* __restrict__ out) {
    __shared__ __align__(16) unsigned char sm[2 * STG_B];
    unsigned smbase = (unsigned)__cvta_generic_to_shared(sm);

    int tid  = threadIdx.x;
    int warp = tid >> 5, lane = tid & 31;
    int wm = warp >> 1, wj = warp & 1;          // 2x2 warp grid
    int gi = lane >> 2, qi = lane & 3;
    int jbase = blockIdx.x * BN1;
    if (jbase > Hh - BN1) jbase = Hh - BN1;     // overlap last block (dup writes benign)
    int kbase = blockIdx.y * 2048;
    int iters = (blockIdx.y == KSPLIT - 1) ? 52 : 64;  // 52*32=1664, 64*32=2048

    // W mapping: 8 float4/thread. chunk c = tid + i*128: row = (tid>>3)+i*16, c8 = tid&7
    int wrow0 = tid >> 3, wc8 = tid & 7;
    const float* wbase = W1 + (size_t)(jbase + wrow0) * LIN + kbase + wc8 * 4;
    unsigned wdst0 = smbase + (unsigned)(wrow0 * ROWB + wc8 * 8);

    // X mapping (cp.async): 2 chunks/thread. row = (tid>>2)+i*32, seg = tid&3
    int xrow0 = tid >> 2, xseg = tid & 3;
    const __nv_bfloat16* xbase = g_xb + (size_t)xrow0 * LIN + kbase + xseg * 8;
    unsigned xdst0 = smbase + (unsigned)(W_BYTES + xrow0 * ROWB + xseg * 16);

    // ldmatrix per-lane offsets (row stride 80B; conflict-free)
    unsigned offA = (unsigned)((lane & 15) * ROWB + (lane >> 4) * 16);
    unsigned offB = (unsigned)((((lane >> 4) & 1) * 8 + (lane & 7)) * ROWB + ((lane >> 3) & 1) * 16);
    unsigned aAddr0 = smbase + W_BYTES + (wm * 32) * ROWB + offA;       // mt=0
    unsigned aAddr1 = aAddr0 + 16 * ROWB;                                // mt=1
    unsigned bAddrB = smbase + (wj * 64) * ROWB + offB;                  // nt pairs at +p*16*ROWB

    float acc[2][8][4];
    #pragma unroll
    for (int a = 0; a < 2; a++)
        #pragma unroll
        for (int b = 0; b < 8; b++)
            #pragma unroll
            for (int q = 0; q < 4; q++) acc[a][b][q] = 0.f;

    // prologue: X stage 0 via cp.async; W iter 0 into registers
    #pragma unroll
    for (int i = 0; i < 2; i++)
        cpa16(xdst0 + i * (32 * ROWB), xbase + (size_t)i * 32 * LIN);
    asm volatile("cp.async.commit_group;");
    float4 wv[8];
    #pragma unroll
    for (int i = 0; i < 8; i++)
        wv[i] = *(const float4*)(wbase + (size_t)i * 16 * LIN);

    #pragma unroll 2
    for (int it = 0; it < iters; it++) {
        unsigned st = (unsigned)(it & 1) * STG_B;
        unsigned sn = (unsigned)((it + 1) & 1) * STG_B;

        // STS: convert W to bf16 (8B per chunk)
        #pragma unroll
        for (int i = 0; i < 8; i++) {
            __nv_bfloat162 p0 = __floats2bfloat162_rn(wv[i].x, wv[i].y);
            __nv_bfloat162 p1 = __floats2bfloat162_rn(wv[i].z, wv[i].w);
            asm volatile("st.shared.v2.b32 [%0], {%1,%2};"
                         :: "r"(wdst0 + st + (unsigned)(i * 16 * ROWB)),
                            "r"(*(unsigned*)&p0), "r"(*(unsigned*)&p1));
        }

        // issue next-iter loads (X cp.async into other stage; W LDG into regs)
        if (it + 1 < iters) {
            int ko = (it + 1) * BK1;
            #pragma unroll
            for (int i = 0; i < 2; i++)
                cpa16(xdst0 + sn + i * (32 * ROWB), xbase + (size_t)i * 32 * LIN + ko);
            #pragma unroll
            for (int i = 0; i < 8; i++)
                wv[i] = *(const float4*)(wbase + (size_t)i * 16 * LIN + ko);
        }
        asm volatile("cp.async.commit_group;");
        asm volatile("cp.async.wait_group 1;");   // current iter's X group done
        __syncthreads();

        // two k16 sub-chunks: per warp 6 LDSM + 16 MMA each
        #pragma unroll
        for (int kk = 0; kk < 2; kk++) {
            unsigned ko = st + (unsigned)(kk * 32);   // 16 halves = 32B
            unsigned a0[2], a1[2], a2[2], a3[2];
            ldsm4(a0[0], a1[0], a2[0], a3[0], aAddr0 + ko);
            ldsm4(a0[1], a1[1], a2[1], a3[1], aAddr1 + ko);
            #pragma unroll
            for (int p = 0; p < 4; p++) {            // n-tile pairs
                unsigned b00, b01, b10, b11;
                ldsm4(b00, b01, b10, b11, bAddrB + ko + (unsigned)(p * 16 * ROWB));
                #pragma unroll
                for (int mt = 0; mt < 2; mt++) {
                    mma16816(acc[mt][p * 2],     a0[mt], a1[mt], a2[mt], a3[mt], b00, b01);
                    mma16816(acc[mt][p * 2 + 1], a0[mt], a1[mt], a2[mt], a3[mt], b10, b11);
                }
            }
        }
        __syncthreads();
    }

    // epilogue: plain STG into split-private partials (dup writes benign)
    float* hp = &g_hpart[blockIdx.y][0][0];
    #pragma unroll
    for (int mt = 0; mt < 2; mt++) {
        #pragma unroll
        for (int nt = 0; nt < 8; nt++) {
            int m = wm * 32 + mt * 16 + gi;
            int j = jbase + wj * 64 + nt * 8 + qi * 2;
            *(float2*)(hp + (size_t)m * Hh + j) =
                make_float2(acc[mt][nt][0], acc[mt][nt][1]);
            *(float2*)(hp + (size_t)(m + 8) * Hh + j) =
                make_float2(acc[mt][nt][2], acc[mt][nt][3]);
        }
    }

    // ---- fused split-K reduce: last CTA of this jblock reduces its strip ----
    __threadfence();
    __syncthreads();
    __shared__ int is_fin;
    if (tid == 0) {
        int old = atomicAdd(&g_jcnt[blockIdx.x], 1);
        is_fin = (old == KSPLIT - 1) ? 1 : 0;
    }
    __syncthreads();

    if (is_fin) {
        int jl = jbase + lane * 4;                      // this lane's float4 column
        // jblock 62 overlaps 61 on j in [7872,7936): mask duplicates
        bool valid = !(blockIdx.x == 62 && lane < 16);
        float4 b1v = valid ? *(const float4*)(b1 + jl) : make_float4(0,0,0,0);
        float4 w2v = valid ? *(const float4*)(W2 + jl) : make_float4(0,0,0,0);
        #pragma unroll
        for (int p = 0; p < 16; p++) {
            int m = p * 4 + warp;                        // 4 warps x 16 passes = 64 m
            float4 hs = make_float4(0.f, 0.f, 0.f, 0.f);
            if (valid) {
                #pragma unroll
                for (int sp = 0; sp < KSPLIT; sp++) {
                    float4 hv = *(const float4*)(&g_hpart[sp][m][jl]);
                    hs.x += hv.x; hs.y += hv.y; hs.z += hv.z; hs.w += hv.w;
                }
            }
            float s = fmaxf(hs.x + b1v.x, 0.f) * w2v.x
                    + fmaxf(hs.y + b1v.y, 0.f) * w2v.y
                    + fmaxf(hs.z + b1v.z, 0.f) * w2v.z
                    + fmaxf(hs.w + b1v.w, 0.f) * w2v.w;
            #pragma unroll
            for (int o = 16; o > 0; o >>= 1) s += __shfl_down_sync(0xffffffffu, s, o);
            if (lane == 0) atomicAdd(&g_lm[m], s);
        }
        __syncthreads();
        if (tid == 0) g_jcnt[blockIdx.x] = 0;            // reset for next replay
    }

    // ---- global last CTA computes the loss ----
    __threadfence();
    __syncthreads();
    __shared__ int is_last;
    if (tid == 0) {
        int old = atomicAdd(&g_done, 1);
        is_last = (old == NCTA1 - 1) ? 1 : 0;
    }
    __syncthreads();
    if (is_last) {
        float per = 0.f;
        if (tid < Bb) {
            float l = g_lm[tid] + b2[0];
            per = (l > 0.f) ? log1pf(expf(-l)) : (log1pf(expf(l)) - l);
        }
        #pragma unroll
        for (int o = 16; o > 0; o >>= 1) per += __shfl_down_sync(0xffffffffu, per, o);
        __shared__ float r2[2];
        if (tid < Bb && (tid & 31) == 0) r2[tid >> 5] = per;
        __syncthreads();
        if (tid == 0) {
            out[0] = (r2[0] + r2[1]) * (1.0f / Bb);
            g_done = 0;                                  // reset for next replay
        }
    }
}

// ---------------------------------------------------------------------------
extern "C" void kernel_launch(void* const* d_in, const int* in_sizes, int n_in,
                              void* d_out, int out_size) {
    const float* feat     = (const float*)d_in[0];
    const float* w        = (const float*)d_in[3];
    const float* bn_gamma = (const float*)d_in[4];
    const float* bn_beta  = (const float*)d_in[5];
    const float* bn_mean  = (const float*)d_in[6];
    const float* bn_var   = (const float*)d_in[7];
    const float* W1       = (const float*)d_in[8];
    const float* b1       = (const float*)d_in[9];
    const float* W2       = (const float*)d_in[10];
    const float* b2       = (const float*)d_in[11];

    k_sort<<<Bb, 512>>>(feat, w);
    dim3 gbn(Bb, 8);
    k_bn<<<gbn, 256>>>(feat, bn_mean, bn_var, bn_gamma, bn_beta);
    dim3 g1(63, KSPLIT);   // 504 CTAs, 4/SM -> one wave
    k_gemm1<<<g1, 128>>>(W1, b1, W2, b2, (float*)d_out);
}

// round 14
// speedup vs baseline: 1.0529x; 1.0529x over previous
#include <cuda_runtime.h>
#include <cuda_bf16.h>
#include <math.h>
#include <stdint.h>

// Problem constants
#define Bb   64
#define NPG  400
#define Kk   250
#define Ff   64
#define LIN  16000
#define Hh   8000
#define Nn   (Bb*NPG)        // 25600
#define BN_EPS 1e-5f

#define KSPLIT 8             // 7 chunks of 2048 + 1 of 1664
#define G2SPLIT 16

// Scratch (device globals; no allocation allowed)
__device__ __nv_bfloat16 g_xb[Bb*LIN];      // bf16 normalized features
__device__ int   g_selidx[Bb*Kk];
__device__ float g_stanh[Bb*Kk];
__device__ float g_hpart[KSPLIT][Bb][Hh];   // split-K partials
__device__ float g_l2[Bb*G2SPLIT];          // gemm2 partial logits
__device__ int   g_done;                    // gemm2 completion counter (zero-init)

// ---------------------------------------------------------------------------
// Kernel: fused scores + bitonic top-K (warp-shuffle inner phases).
// Final order: value descending, index ascending on ties.
// ---------------------------------------------------------------------------
__global__ void k_sort(const float* __restrict__ feat, const float* __restrict__ w) {
    __shared__ float sv[512];
    __shared__ int   si[512];
    __shared__ float s_inv;
    int tid = threadIdx.x, b = blockIdx.x;
    int warp = tid >> 5, lane = tid & 31;

    if (tid == 0) {
        float s = 0.f;
        #pragma unroll
        for (int i = 0; i < Ff; i++) s += w[i] * w[i];
        s_inv = rsqrtf(s);
    }
    const float* xg = feat + (size_t)11 * Nn * Ff + (size_t)b * NPG * Ff;
    float wl0 = w[lane], wl1 = w[lane + 32];
    for (int nd = warp; nd < NPG; nd += 16) {
        const float* x = xg + (size_t)nd * Ff;
        float v = x[lane] * wl0 + x[lane + 32] * wl1;
        #pragma unroll
        for (int o = 16; o > 0; o >>= 1) v += __shfl_down_sync(0xffffffffu, v, o);
        if (lane == 0) sv[nd] = v;
    }
    if (tid >= NPG) sv[tid] = __int_as_float(0xff800000);   // -inf pad
    __syncthreads();

    float v = sv[tid];
    int   idx = tid;

    // k = 2..32: all partners intra-warp -> pure shfl, no barriers
    #pragma unroll
    for (int k = 2; k <= 32; k <<= 1) {
        bool up = ((tid & k) == 0);
        #pragma unroll
        for (int j = k >> 1; j > 0; j >>= 1) {
            float vb = __shfl_xor_sync(0xffffffffu, v, j);
            int   ib = __shfl_xor_sync(0xffffffffu, idx, j);
            bool lowerLane = ((tid & j) == 0);
            bool pre = (v > vb) || (v == vb && idx < ib);    // mine precedes (desc order)
            bool sw = (up == lowerLane) ? !pre : pre;
            if (sw) { v = vb; idx = ib; }
        }
    }

    // k = 64..512: smem phases for j>=32, then shfl for j<=16
    for (int k = 64; k <= 512; k <<= 1) {
        sv[tid] = v; si[tid] = idx;
        __syncthreads();
        for (int j = k >> 1; j >= 32; j >>= 1) {
            int ixj = tid ^ j;
            if (ixj > tid) {
                float va = sv[tid], vb2 = sv[ixj];
                int   ia = si[tid], ib2 = si[ixj];
                bool aFirst = (va > vb2) || (va == vb2 && ia < ib2);
                bool desc = ((tid & k) == 0);
                bool sw = desc ? !aFirst : aFirst;
                if (sw) { sv[tid] = vb2; sv[ixj] = va; si[tid] = ib2; si[ixj] = ia; }
            }
            __syncthreads();
        }
        v = sv[tid]; idx = si[tid];
        bool up = ((tid & k) == 0);
        #pragma unroll
        for (int j = 16; j > 0; j >>= 1) {
            float vb = __shfl_xor_sync(0xffffffffu, v, j);
            int   ib = __shfl_xor_sync(0xffffffffu, idx, j);
            bool lowerLane = ((tid & j) == 0);
            bool pre = (v > vb) || (v == vb && idx < ib);
            bool sw = (up == lowerLane) ? !pre : pre;
            if (sw) { v = vb; idx = ib; }
        }
    }

    if (tid < Kk) {
        g_selidx[b * Kk + tid] = idx;
        g_stanh[b * Kk + tid]  = tanhf(v * s_inv);
    }
}

// ---------------------------------------------------------------------------
// Kernel: gather + BatchNorm -> bf16 xn   grid (64, 8)
// ---------------------------------------------------------------------------
__global__ void k_bn(const float* __restrict__ feat,
                     const float* __restrict__ bn_mean, const float* __restrict__ bn_var,
                     const float* __restrict__ bn_gamma, const float* __restrict__ bn_beta) {
    int b = blockIdx.x, q = blockIdx.y, tid = threadIdx.x;
    const float* xg = feat + (size_t)11 * Nn * Ff + (size_t)b * NPG * Ff;
    int base = q * (LIN / 8);
    for (int t = tid; t < LIN / 8; t += 256) {
        int i = base + t;
        int r = i >> 6, f = i & 63;
        int idx = g_selidx[b * Kk + r];
        float st = g_stanh[b * Kk + r];
        float xv = xg[idx * Ff + f];
        float xn = (xv * st - bn_mean[i]) * rsqrtf(bn_var[i] + BN_EPS) * bn_gamma[i] + bn_beta[i];
        g_xb[(size_t)b * LIN + i] = __float2bfloat16(xn);
    }
}

// ---------------------------------------------------------------------------
// GEMM1 (frozen R12 structure):  hpart[s][m][j] = sum_{k chunk s} xn[m,k]*W1[j,k]
// 128 thr (4 warps), warp tile 32m x 64j, BN=128, BK=32, 2-stage smem,
// 4 CTAs/SM. W: LDG fp32 -> bf16 regs -> STS. X: cp.async.
// grid (63, 8) = 504 CTAs, one wave. Last j-block overlaps (benign dup writes).
// ---------------------------------------------------------------------------
#define BN1   128
#define BK1   32
#define ROWB  80                    // bytes per smem row (40 halves)
#define W_BYTES (128 * ROWB)        // 10240
#define X_BYTES (64 * ROWB)         // 5120
#define STG_B   (W_BYTES + X_BYTES) // 15360

__device__ __forceinline__ void mma16816(float* d,
                                         unsigned a0, unsigned a1, unsigned a2, unsigned a3,
                                         unsigned b0, unsigned b1) {
    asm volatile(
        "mma.sync.aligned.m16n8k16.row.col.f32.bf16.bf16.f32 "
        "{%0,%1,%2,%3}, {%4,%5,%6,%7}, {%8,%9}, {%0,%1,%2,%3};\n"
        : "+f"(d[0]), "+f"(d[1]), "+f"(d[2]), "+f"(d[3])
        : "r"(a0), "r"(a1), "r"(a2), "r"(a3), "r"(b0), "r"(b1));
}

__device__ __forceinline__ void ldsm4(unsigned& r0, unsigned& r1, unsigned& r2, unsigned& r3,
                                      unsigned addr) {
    asm volatile("ldmatrix.sync.aligned.m8n8.x4.shared.b16 {%0,%1,%2,%3}, [%4];"
                 : "=r"(r0), "=r"(r1), "=r"(r2), "=r"(r3) : "r"(addr));
}

__device__ __forceinline__ void cpa16(unsigned dst, const void* src) {
    asm volatile("cp.async.cg.shared.global [%0], [%1], 16;" :: "r"(dst), "l"(src));
}

__global__ __launch_bounds__(128, 4) void k_gemm1(const float* __restrict__ W1) {
    __shared__ __align__(16) unsigned char sm[2 * STG_B];
    unsigned smbase = (unsigned)__cvta_generic_to_shared(sm);

    int tid  = threadIdx.x;
    int warp = tid >> 5, lane = tid & 31;
    int wm = warp >> 1, wj = warp & 1;          // 2x2 warp grid
    int gi = lane >> 2, qi = lane & 3;
    int jbase = blockIdx.x * BN1;
    if (jbase > Hh - BN1) jbase = Hh - BN1;     // overlap last block (dup writes benign)
    int kbase = blockIdx.y * 2048;
    int iters = (blockIdx.y == KSPLIT - 1) ? 52 : 64;  // 52*32=1664, 64*32=2048

    // W mapping: 8 float4/thread. chunk c = tid + i*128: row = (tid>>3)+i*16, c8 = tid&7
    int wrow0 = tid >> 3, wc8 = tid & 7;
    const float* wbase = W1 + (size_t)(jbase + wrow0) * LIN + kbase + wc8 * 4;
    unsigned wdst0 = smbase + (unsigned)(wrow0 * ROWB + wc8 * 8);

    // X mapping (cp.async): 2 chunks/thread. row = (tid>>2)+i*32, seg = tid&3
    int xrow0 = tid >> 2, xseg = tid & 3;
    const __nv_bfloat16* xbase = g_xb + (size_t)xrow0 * LIN + kbase + xseg * 8;
    unsigned xdst0 = smbase + (unsigned)(W_BYTES + xrow0 * ROWB + xseg * 16);

    // ldmatrix per-lane offsets (row stride 80B; conflict-free)
    unsigned offA = (unsigned)((lane & 15) * ROWB + (lane >> 4) * 16);
    unsigned offB = (unsigned)((((lane >> 4) & 1) * 8 + (lane & 7)) * ROWB + ((lane >> 3) & 1) * 16);
    unsigned aAddr0 = smbase + W_BYTES + (wm * 32) * ROWB + offA;       // mt=0
    unsigned aAddr1 = aAddr0 + 16 * ROWB;                                // mt=1
    unsigned bAddrB = smbase + (wj * 64) * ROWB + offB;                  // nt pairs at +p*16*ROWB

    float acc[2][8][4];
    #pragma unroll
    for (int a = 0; a < 2; a++)
        #pragma unroll
        for (int b = 0; b < 8; b++)
            #pragma unroll
            for (int q = 0; q < 4; q++) acc[a][b][q] = 0.f;

    // prologue: X stage 0 via cp.async; W iter 0 into registers
    #pragma unroll
    for (int i = 0; i < 2; i++)
        cpa16(xdst0 + i * (32 * ROWB), xbase + (size_t)i * 32 * LIN);
    asm volatile("cp.async.commit_group;");
    float4 wv[8];
    #pragma unroll
    for (int i = 0; i < 8; i++)
        wv[i] = *(const float4*)(wbase + (size_t)i * 16 * LIN);

    #pragma unroll 2
    for (int it = 0; it < iters; it++) {
        unsigned st = (unsigned)(it & 1) * STG_B;
        unsigned sn = (unsigned)((it + 1) & 1) * STG_B;

        // STS: convert W to bf16 (8B per chunk)
        #pragma unroll
        for (int i = 0; i < 8; i++) {
            __nv_bfloat162 p0 = __floats2bfloat162_rn(wv[i].x, wv[i].y);
            __nv_bfloat162 p1 = __floats2bfloat162_rn(wv[i].z, wv[i].w);
            asm volatile("st.shared.v2.b32 [%0], {%1,%2};"
                         :: "r"(wdst0 + st + (unsigned)(i * 16 * ROWB)),
                            "r"(*(unsigned*)&p0), "r"(*(unsigned*)&p1));
        }

        // issue next-iter loads (X cp.async into other stage; W LDG into regs)
        if (it + 1 < iters) {
            int ko = (it + 1) * BK1;
            #pragma unroll
            for (int i = 0; i < 2; i++)
                cpa16(xdst0 + sn + i * (32 * ROWB), xbase + (size_t)i * 32 * LIN + ko);
            #pragma unroll
            for (int i = 0; i < 8; i++)
                wv[i] = *(const float4*)(wbase + (size_t)i * 16 * LIN + ko);
        }
        asm volatile("cp.async.commit_group;");
        asm volatile("cp.async.wait_group 1;");   // current iter's X group done
        __syncthreads();

        // two k16 sub-chunks: per warp 6 LDSM + 16 MMA each
        #pragma unroll
        for (int kk = 0; kk < 2; kk++) {
            unsigned ko = st + (unsigned)(kk * 32);   // 16 halves = 32B
            unsigned a0[2], a1[2], a2[2], a3[2];
            ldsm4(a0[0], a1[0], a2[0], a3[0], aAddr0 + ko);
            ldsm4(a0[1], a1[1], a2[1], a3[1], aAddr1 + ko);
            #pragma unroll
            for (int p = 0; p < 4; p++) {            // n-tile pairs
                unsigned b00, b01, b10, b11;
                ldsm4(b00, b01, b10, b11, bAddrB + ko + (unsigned)(p * 16 * ROWB));
                #pragma unroll
                for (int mt = 0; mt < 2; mt++) {
                    mma16816(acc[mt][p * 2],     a0[mt], a1[mt], a2[mt], a3[mt], b00, b01);
                    mma16816(acc[mt][p * 2 + 1], a0[mt], a1[mt], a2[mt], a3[mt], b10, b11);
                }
            }
        }
        __syncthreads();
    }

    // epilogue: plain STG into split-private partials (no guard; overlap benign)
    float* hp = &g_hpart[blockIdx.y][0][0];
    #pragma unroll
    for (int mt = 0; mt < 2; mt++) {
        #pragma unroll
        for (int nt = 0; nt < 8; nt++) {
            int m = wm * 32 + mt * 16 + gi;
            int j = jbase + wj * 64 + nt * 8 + qi * 2;
            *(float2*)(hp + (size_t)m * Hh + j) =
                make_float2(acc[mt][nt][0], acc[mt][nt][1]);
            *(float2*)(hp + (size_t)(m + 8) * Hh + j) =
                make_float2(acc[mt][nt][2], acc[mt][nt][3]);
        }
    }
}

// ---------------------------------------------------------------------------
// GEMM2 + split-reduce + bias + relu + (last block) loss. grid (64,16), 256 thr.
// ---------------------------------------------------------------------------
__global__ void k_gemm2(const float* __restrict__ b1, const float* __restrict__ W2,
                        const float* __restrict__ b2, float* __restrict__ out) {
    int m = blockIdx.x, q = blockIdx.y, tid = threadIdx.x;
    int jq = q * (Hh / G2SPLIT);          // 500 per split
    float s = 0.f;
    for (int t = tid * 4; t < Hh / G2SPLIT; t += 1024) {
        int j = jq + t;
        float4 hs = make_float4(0.f, 0.f, 0.f, 0.f);
        #pragma unroll
        for (int sp = 0; sp < KSPLIT; sp++) {
            float4 hv = *(const float4*)(&g_hpart[sp][m][j]);
            hs.x += hv.x; hs.y += hv.y; hs.z += hv.z; hs.w += hv.w;
        }
        float4 bv = *(const float4*)(b1 + j);
        float4 wv = *(const float4*)(W2 + j);
        s += fmaxf(hs.x + bv.x, 0.f) * wv.x;
        s += fmaxf(hs.y + bv.y, 0.f) * wv.y;
        s += fmaxf(hs.z + bv.z, 0.f) * wv.z;
        s += fmaxf(hs.w + bv.w, 0.f) * wv.w;
    }
    #pragma unroll
    for (int o = 16; o > 0; o >>= 1) s += __shfl_down_sync(0xffffffffu, s, o);
    __shared__ float red[8];
    if ((tid & 31) == 0) red[tid >> 5] = s;
    __syncthreads();
    if (tid == 0) {
        float t8 = 0.f;
        #pragma unroll
        for (int i = 0; i < 8; i++) t8 += red[i];
        g_l2[m * G2SPLIT + q] = t8;
    }

    // last-block loss: writers fence before count; count-full implies all
    // g_l2 stores visible to the last block.
    __shared__ int is_last;
    __threadfence();
    if (tid == 0) {
        int old = atomicAdd(&g_done, 1);
        is_last = (old == Bb * G2SPLIT - 1) ? 1 : 0;
    }
    __syncthreads();
    if (is_last) {
        float per = 0.f;
        if (tid < Bb) {
            float l = b2[0];
            #pragma unroll
            for (int qq = 0; qq < G2SPLIT; qq++) l += g_l2[tid * G2SPLIT + qq];
            per = (l > 0.f) ? log1pf(expf(-l)) : (log1pf(expf(l)) - l);
        }
        #pragma unroll
        for (int o = 16; o > 0; o >>= 1) per += __shfl_down_sync(0xffffffffu, per, o);
        __shared__ float r2[2];
        if (tid < Bb && (tid & 31) == 0) r2[tid >> 5] = per;
        __syncthreads();
        if (tid == 0) {
            out[0] = (r2[0] + r2[1]) * (1.0f / Bb);
            g_done = 0;   // reset for graph replay determinism
        }
    }
}

// ---------------------------------------------------------------------------
extern "C" void kernel_launch(void* const* d_in, const int* in_sizes, int n_in,
                              void* d_out, int out_size) {
    const float* feat     = (const float*)d_in[0];
    const float* w        = (const float*)d_in[3];
    const float* bn_gamma = (const float*)d_in[4];
    const float* bn_beta  = (const float*)d_in[5];
    const float* bn_mean  = (const float*)d_in[6];
    const float* bn_var   = (const float*)d_in[7];
    const float* W1       = (const float*)d_in[8];
    const float* b1       = (const float*)d_in[9];
    const float* W2       = (const float*)d_in[10];
    const float* b2       = (const float*)d_in[11];

    k_sort<<<Bb, 512>>>(feat, w);
    dim3 gbn(Bb, 8);
    k_bn<<<gbn, 256>>>(feat, bn_mean, bn_var, bn_gamma, bn_beta);
    dim3 g1(63, KSPLIT);   // 504 CTAs, 4/SM -> one wave
    k_gemm1<<<g1, 128>>>(W1);
    dim3 g2(Bb, G2SPLIT);
    k_gemm2<<<g2, 256>>>(b1, W2, b2, (float*)d_out);
}

// round 15
// speedup vs baseline: 1.1023x; 1.0469x over previous
#include <cuda_runtime.h>
#include <cuda_bf16.h>
#include <math.h>
#include <stdint.h>

// Problem constants
#define Bb   64
#define NPG  400
#define Kk   250
#define Ff   64
#define LIN  16000
#define Hh   8000
#define Nn   (Bb*NPG)        // 25600
#define BN_EPS 1e-5f

#define KSPLIT 8             // 7 chunks of 2048 + 1 of 1664
#define G2SPLIT 8

// Scratch (device globals; no allocation allowed)
__device__ __nv_bfloat16 g_xb[Bb*LIN];      // bf16 normalized features
__device__ int   g_selidx[Bb*Kk];
__device__ float g_stanh[Bb*Kk];
__device__ float g_hpart[KSPLIT][Bb][Hh];   // split-K partials
__device__ float g_lm[Bb];                  // per-m logit accumulators (self-resetting)
__device__ int   g_cntm[Bb];                // per-m arrival counters (self-resetting)
__device__ float g_loss;                    // loss accumulator (self-resetting)
__device__ int   g_done;                    // global arrival counter (self-resetting)

// ---------------------------------------------------------------------------
// Kernel: scores (per-thread serial dot) + bitonic top-K (warp-shuffle phases)
// Final order: value descending, index ascending on ties.
// ---------------------------------------------------------------------------
__global__ void k_sort(const float* __restrict__ feat, const float* __restrict__ w) {
    __shared__ float sv[512];
    __shared__ int   si[512];
    __shared__ float s_inv;
    int tid = threadIdx.x, b = blockIdx.x;

    if (tid == 0) {
        float s = 0.f;
        #pragma unroll
        for (int i = 0; i < Ff; i++) s += w[i] * w[i];
        s_inv = rsqrtf(s);
    }
    const float* xg = feat + (size_t)11 * Nn * Ff + (size_t)b * NPG * Ff;

    // score: thread t owns node t (16 float4 dot, no shuffles)
    float v = __int_as_float(0xff800000);   // -inf pad
    if (tid < NPG) {
        const float* x = xg + (size_t)tid * Ff;
        float s = 0.f;
        #pragma unroll
        for (int i = 0; i < 16; i++) {
            float4 xv = *(const float4*)(x + i * 4);
            float4 wv = *(const float4*)(w + i * 4);
            s += xv.x * wv.x + xv.y * wv.y + xv.z * wv.z + xv.w * wv.w;
        }
        v = s;
    }
    int idx = tid;

    // k = 2..32: all partners intra-warp -> pure shfl, no barriers
    #pragma unroll
    for (int k = 2; k <= 32; k <<= 1) {
        bool up = ((tid & k) == 0);
        #pragma unroll
        for (int j = k >> 1; j > 0; j >>= 1) {
            float vb = __shfl_xor_sync(0xffffffffu, v, j);
            int   ib = __shfl_xor_sync(0xffffffffu, idx, j);
            bool lowerLane = ((tid & j) == 0);
            bool pre = (v > vb) || (v == vb && idx < ib);    // mine precedes (desc)
            bool sw = (up == lowerLane) ? !pre : pre;
            if (sw) { v = vb; idx = ib; }
        }
    }

    // k = 64..512: smem phases for j>=32, then shfl for j<=16
    for (int k = 64; k <= 512; k <<= 1) {
        sv[tid] = v; si[tid] = idx;
        __syncthreads();
        for (int j = k >> 1; j >= 32; j >>= 1) {
            int ixj = tid ^ j;
            if (ixj > tid) {
                float va = sv[tid], vb2 = sv[ixj];
                int   ia = si[tid], ib2 = si[ixj];
                bool aFirst = (va > vb2) || (va == vb2 && ia < ib2);
                bool desc = ((tid & k) == 0);
                bool sw = desc ? !aFirst : aFirst;
                if (sw) { sv[tid] = vb2; sv[ixj] = va; si[tid] = ib2; si[ixj] = ia; }
            }
            __syncthreads();
        }
        v = sv[tid]; idx = si[tid];
        bool up = ((tid & k) == 0);
        #pragma unroll
        for (int j = 16; j > 0; j >>= 1) {
            float vb = __shfl_xor_sync(0xffffffffu, v, j);
            int   ib = __shfl_xor_sync(0xffffffffu, idx, j);
            bool lowerLane = ((tid & j) == 0);
            bool pre = (v > vb) || (v == vb && idx < ib);
            bool sw = (up == lowerLane) ? !pre : pre;
            if (sw) { v = vb; idx = ib; }
        }
    }

    if (tid < Kk) {
        g_selidx[b * Kk + tid] = idx;
        g_stanh[b * Kk + tid]  = tanhf(v * s_inv);
    }
}

// ---------------------------------------------------------------------------
// Kernel: gather + BatchNorm -> bf16 xn   grid (64, 16)
// ---------------------------------------------------------------------------
__global__ void k_bn(const float* __restrict__ feat,
                     const float* __restrict__ bn_mean, const float* __restrict__ bn_var,
                     const float* __restrict__ bn_gamma, const float* __restrict__ bn_beta) {
    int b = blockIdx.x, q = blockIdx.y, tid = threadIdx.x;
    const float* xg = feat + (size_t)11 * Nn * Ff + (size_t)b * NPG * Ff;
    int base = q * (LIN / 16);
    for (int t = tid; t < LIN / 16; t += 256) {
        int i = base + t;
        int r = i >> 6, f = i & 63;
        int idx = g_selidx[b * Kk + r];
        float st = g_stanh[b * Kk + r];
        float xv = xg[idx * Ff + f];
        float xn = (xv * st - bn_mean[i]) * rsqrtf(bn_var[i] + BN_EPS) * bn_gamma[i] + bn_beta[i];
        g_xb[(size_t)b * LIN + i] = __float2bfloat16(xn);
    }
}

// ---------------------------------------------------------------------------
// GEMM1 (frozen R12 structure):  hpart[s][m][j] = sum_{k chunk s} xn[m,k]*W1[j,k]
// 128 thr (4 warps), warp tile 32m x 64j, BN=128, BK=32, 2-stage smem,
// 4 CTAs/SM. W: LDG fp32 -> bf16 regs -> STS. X: cp.async.
// grid (63, 8) = 504 CTAs, one wave. Last j-block overlaps (benign dup writes).
// ---------------------------------------------------------------------------
#define BN1   128
#define BK1   32
#define ROWB  80                    // bytes per smem row (40 halves)
#define W_BYTES (128 * ROWB)        // 10240
#define X_BYTES (64 * ROWB)         // 5120
#define STG_B   (W_BYTES + X_BYTES) // 15360

__device__ __forceinline__ void mma16816(float* d,
                                         unsigned a0, unsigned a1, unsigned a2, unsigned a3,
                                         unsigned b0, unsigned b1) {
    asm volatile(
        "mma.sync.aligned.m16n8k16.row.col.f32.bf16.bf16.f32 "
        "{%0,%1,%2,%3}, {%4,%5,%6,%7}, {%8,%9}, {%0,%1,%2,%3};\n"
        : "+f"(d[0]), "+f"(d[1]), "+f"(d[2]), "+f"(d[3])
        : "r"(a0), "r"(a1), "r"(a2), "r"(a3), "r"(b0), "r"(b1));
}

__device__ __forceinline__ void ldsm4(unsigned& r0, unsigned& r1, unsigned& r2, unsigned& r3,
                                      unsigned addr) {
    asm volatile("ldmatrix.sync.aligned.m8n8.x4.shared.b16 {%0,%1,%2,%3}, [%4];"
                 : "=r"(r0), "=r"(r1), "=r"(r2), "=r"(r3) : "r"(addr));
}

__device__ __forceinline__ void cpa16(unsigned dst, const void* src) {
    asm volatile("cp.async.cg.shared.global [%0], [%1], 16;" :: "r"(dst), "l"(src));
}

__global__ __launch_bounds__(128, 4) void k_gemm1(const float* __restrict__ W1) {
    __shared__ __align__(16) unsigned char sm[2 * STG_B];
    unsigned smbase = (unsigned)__cvta_generic_to_shared(sm);

    int tid  = threadIdx.x;
    int warp = tid >> 5, lane = tid & 31;
    int wm = warp >> 1, wj = warp & 1;          // 2x2 warp grid
    int gi = lane >> 2, qi = lane & 3;
    int jbase = blockIdx.x * BN1;
    if (jbase > Hh - BN1) jbase = Hh - BN1;     // overlap last block (dup writes benign)
    int kbase = blockIdx.y * 2048;
    int iters = (blockIdx.y == KSPLIT - 1) ? 52 : 64;  // 52*32=1664, 64*32=2048

    // W mapping: 8 float4/thread. chunk c = tid + i*128: row = (tid>>3)+i*16, c8 = tid&7
    int wrow0 = tid >> 3, wc8 = tid & 7;
    const float* wbase = W1 + (size_t)(jbase + wrow0) * LIN + kbase + wc8 * 4;
    unsigned wdst0 = smbase + (unsigned)(wrow0 * ROWB + wc8 * 8);

    // X mapping (cp.async): 2 chunks/thread. row = (tid>>2)+i*32, seg = tid&3
    int xrow0 = tid >> 2, xseg = tid & 3;
    const __nv_bfloat16* xbase = g_xb + (size_t)xrow0 * LIN + kbase + xseg * 8;
    unsigned xdst0 = smbase + (unsigned)(W_BYTES + xrow0 * ROWB + xseg * 16);

    // ldmatrix per-lane offsets (row stride 80B; conflict-free)
    unsigned offA = (unsigned)((lane & 15) * ROWB + (lane >> 4) * 16);
    unsigned offB = (unsigned)((((lane >> 4) & 1) * 8 + (lane & 7)) * ROWB + ((lane >> 3) & 1) * 16);
    unsigned aAddr0 = smbase + W_BYTES + (wm * 32) * ROWB + offA;       // mt=0
    unsigned aAddr1 = aAddr0 + 16 * ROWB;                                // mt=1
    unsigned bAddrB = smbase + (wj * 64) * ROWB + offB;                  // nt pairs at +p*16*ROWB

    float acc[2][8][4];
    #pragma unroll
    for (int a = 0; a < 2; a++)
        #pragma unroll
        for (int b = 0; b < 8; b++)
            #pragma unroll
            for (int q = 0; q < 4; q++) acc[a][b][q] = 0.f;

    // prologue: X stage 0 via cp.async; W iter 0 into registers
    #pragma unroll
    for (int i = 0; i < 2; i++)
        cpa16(xdst0 + i * (32 * ROWB), xbase + (size_t)i * 32 * LIN);
    asm volatile("cp.async.commit_group;");
    float4 wv[8];
    #pragma unroll
    for (int i = 0; i < 8; i++)
        wv[i] = *(const float4*)(wbase + (size_t)i * 16 * LIN);

    #pragma unroll 2
    for (int it = 0; it < iters; it++) {
        unsigned st = (unsigned)(it & 1) * STG_B;
        unsigned sn = (unsigned)((it + 1) & 1) * STG_B;

        // STS: convert W to bf16 (8B per chunk)
        #pragma unroll
        for (int i = 0; i < 8; i++) {
            __nv_bfloat162 p0 = __floats2bfloat162_rn(wv[i].x, wv[i].y);
            __nv_bfloat162 p1 = __floats2bfloat162_rn(wv[i].z, wv[i].w);
            asm volatile("st.shared.v2.b32 [%0], {%1,%2};"
                         :: "r"(wdst0 + st + (unsigned)(i * 16 * ROWB)),
                            "r"(*(unsigned*)&p0), "r"(*(unsigned*)&p1));
        }

        // issue next-iter loads (X cp.async into other stage; W LDG into regs)
        if (it + 1 < iters) {
            int ko = (it + 1) * BK1;
            #pragma unroll
            for (int i = 0; i < 2; i++)
                cpa16(xdst0 + sn + i * (32 * ROWB), xbase + (size_t)i * 32 * LIN + ko);
            #pragma unroll
            for (int i = 0; i < 8; i++)
                wv[i] = *(const float4*)(wbase + (size_t)i * 16 * LIN + ko);
        }
        asm volatile("cp.async.commit_group;");
        asm volatile("cp.async.wait_group 1;");   // current iter's X group done
        __syncthreads();

        // two k16 sub-chunks: per warp 6 LDSM + 16 MMA each
        #pragma unroll
        for (int kk = 0; kk < 2; kk++) {
            unsigned ko = st + (unsigned)(kk * 32);   // 16 halves = 32B
            unsigned a0[2], a1[2], a2[2], a3[2];
            ldsm4(a0[0], a1[0], a2[0], a3[0], aAddr0 + ko);
            ldsm4(a0[1], a1[1], a2[1], a3[1], aAddr1 + ko);
            #pragma unroll
            for (int p = 0; p < 4; p++) {            // n-tile pairs
                unsigned b00, b01, b10, b11;
                ldsm4(b00, b01, b10, b11, bAddrB + ko + (unsigned)(p * 16 * ROWB));
                #pragma unroll
                for (int mt = 0; mt < 2; mt++) {
                    mma16816(acc[mt][p * 2],     a0[mt], a1[mt], a2[mt], a3[mt], b00, b01);
                    mma16816(acc[mt][p * 2 + 1], a0[mt], a1[mt], a2[mt], a3[mt], b10, b11);
                }
            }
        }
        __syncthreads();
    }

    // epilogue: plain STG into split-private partials (no guard; overlap benign)
    float* hp = &g_hpart[blockIdx.y][0][0];
    #pragma unroll
    for (int mt = 0; mt < 2; mt++) {
        #pragma unroll
        for (int nt = 0; nt < 8; nt++) {
            int m = wm * 32 + mt * 16 + gi;
            int j = jbase + wj * 64 + nt * 8 + qi * 2;
            *(float2*)(hp + (size_t)m * Hh + j) =
                make_float2(acc[mt][nt][0], acc[mt][nt][1]);
            *(float2*)(hp + (size_t)(m + 8) * Hh + j) =
                make_float2(acc[mt][nt][2], acc[mt][nt][3]);
        }
    }
}

// ---------------------------------------------------------------------------
// GEMM2 + split-reduce + bias + relu + hierarchical-atomic loss.
// grid (64, 8), 256 thr. Block (m,q): j in [q*1000, q*1000+1000).
// Tree: block -> g_lm[m] (8 arrivals) -> per-m last: softplus -> g_loss
// (64 arrivals) -> global last writes out. All counters self-reset.
// ---------------------------------------------------------------------------
__global__ void k_gemm2(const float* __restrict__ b1, const float* __restrict__ W2,
                        const float* __restrict__ b2, float* __restrict__ out) {
    int m = blockIdx.x, q = blockIdx.y, tid = threadIdx.x;
    float s = 0.f;
    int t = tid * 4;
    if (t < Hh / G2SPLIT) {                  // 250 of 256 threads active
        int j = q * (Hh / G2SPLIT) + t;
        float4 hs = make_float4(0.f, 0.f, 0.f, 0.f);
        #pragma unroll
        for (int sp = 0; sp < KSPLIT; sp++) {
            float4 hv = *(const float4*)(&g_hpart[sp][m][j]);
            hs.x += hv.x; hs.y += hv.y; hs.z += hv.z; hs.w += hv.w;
        }
        float4 bv = *(const float4*)(b1 + j);
        float4 wv = *(const float4*)(W2 + j);
        s += fmaxf(hs.x + bv.x, 0.f) * wv.x;
        s += fmaxf(hs.y + bv.y, 0.f) * wv.y;
        s += fmaxf(hs.z + bv.z, 0.f) * wv.z;
        s += fmaxf(hs.w + bv.w, 0.f) * wv.w;
    }
    #pragma unroll
    for (int o = 16; o > 0; o >>= 1) s += __shfl_down_sync(0xffffffffu, s, o);
    __shared__ float red[8];
    if ((tid & 31) == 0) red[tid >> 5] = s;
    __syncthreads();

    if (tid == 0) {
        float tot = 0.f;
        #pragma unroll
        for (int i = 0; i < 8; i++) tot += red[i];
        atomicAdd(&g_lm[m], tot);
        __threadfence();
        int old = atomicAdd(&g_cntm[m], 1);
        if (old == G2SPLIT - 1) {
            // last block of this m: all 8 adds to g_lm[m] are visible
            float l = atomicAdd(&g_lm[m], 0.f) + b2[0];
            float per = (l > 0.f) ? log1pf(expf(-l)) : (log1pf(expf(l)) - l);
            atomicAdd(&g_loss, per);
            __threadfence();
            int o2 = atomicAdd(&g_done, 1);
            if (o2 == Bb - 1) {
                out[0] = atomicAdd(&g_loss, 0.f) * (1.0f / Bb);
                g_loss = 0.f;               // reset for next graph replay
                g_done = 0;
            }
            g_lm[m] = 0.f;                  // self-reset
            g_cntm[m] = 0;
        }
    }
}

// ---------------------------------------------------------------------------
extern "C" void kernel_launch(void* const* d_in, const int* in_sizes, int n_in,
                              void* d_out, int out_size) {
    const float* feat     = (const float*)d_in[0];
    const float* w        = (const float*)d_in[3];
    const float* bn_gamma = (const float*)d_in[4];
    const float* bn_beta  = (const float*)d_in[5];
    const float* bn_mean  = (const float*)d_in[6];
    const float* bn_var   = (const float*)d_in[7];
    const float* W1       = (const float*)d_in[8];
    const float* b1       = (const float*)d_in[9];
    const float* W2       = (const float*)d_in[10];
    const float* b2       = (const float*)d_in[11];

    k_sort<<<Bb, 512>>>(feat, w);
    dim3 gbn(Bb, 16);
    k_bn<<<gbn, 256>>>(feat, bn_mean, bn_var, bn_gamma, bn_beta);
    dim3 g1(63, KSPLIT);   // 504 CTAs, 4/SM -> one wave
    k_gemm1<<<g1, 128>>>(W1);
    dim3 g2(Bb, G2SPLIT);
    k_gemm2<<<g2, 256>>>(b1, W2, b2, (float*)d_out);
}

// round 16
// speedup vs baseline: 1.1040x; 1.0016x over previous
#include <cuda_runtime.h>
#include <cuda_bf16.h>
#include <math.h>
#include <stdint.h>

// Problem constants
#define Bb   64
#define NPG  400
#define Kk   250
#define Ff   64
#define LIN  16000
#define Hh   8000
#define Nn   (Bb*NPG)        // 25600
#define BN_EPS 1e-5f

#define KSPLIT 8             // 7 chunks of 2048 + 1 of 1664
#define G2SPLIT 8

// Scratch (device globals; no allocation allowed)
__device__ __nv_bfloat16 g_xb[Bb*LIN];      // bf16 normalized features
__device__ int   g_selidx[Bb*Kk];
__device__ float g_stanh[Bb*Kk];
__device__ __nv_bfloat16 g_hb[KSPLIT][Bb][Hh];  // split-K partials (bf16)
__device__ float g_lm[Bb];                  // per-m logit accumulators (self-resetting)
__device__ int   g_cntm[Bb];                // per-m arrival counters (self-resetting)
__device__ float g_loss;                    // loss accumulator (self-resetting)
__device__ int   g_done;                    // global arrival counter (self-resetting)

// ---------------------------------------------------------------------------
// Kernel: scores (per-thread serial dot) + bitonic top-K (warp-shuffle phases)
// Final order: value descending, index ascending on ties.
// ---------------------------------------------------------------------------
__global__ void k_sort(const float* __restrict__ feat, const float* __restrict__ w) {
    __shared__ float sv[512];
    __shared__ int   si[512];
    __shared__ float s_inv;
    int tid = threadIdx.x, b = blockIdx.x;

    if (tid == 0) {
        float s = 0.f;
        #pragma unroll
        for (int i = 0; i < Ff; i++) s += w[i] * w[i];
        s_inv = rsqrtf(s);
    }
    const float* xg = feat + (size_t)11 * Nn * Ff + (size_t)b * NPG * Ff;

    // score: thread t owns node t (16 float4 dot, no shuffles)
    float v = __int_as_float(0xff800000);   // -inf pad
    if (tid < NPG) {
        const float* x = xg + (size_t)tid * Ff;
        float s = 0.f;
        #pragma unroll
        for (int i = 0; i < 16; i++) {
            float4 xv = *(const float4*)(x + i * 4);
            float4 wv = *(const float4*)(w + i * 4);
            s += xv.x * wv.x + xv.y * wv.y + xv.z * wv.z + xv.w * wv.w;
        }
        v = s;
    }
    int idx = tid;

    // k = 2..32: all partners intra-warp -> pure shfl, no barriers
    #pragma unroll
    for (int k = 2; k <= 32; k <<= 1) {
        bool up = ((tid & k) == 0);
        #pragma unroll
        for (int j = k >> 1; j > 0; j >>= 1) {
            float vb = __shfl_xor_sync(0xffffffffu, v, j);
            int   ib = __shfl_xor_sync(0xffffffffu, idx, j);
            bool lowerLane = ((tid & j) == 0);
            bool pre = (v > vb) || (v == vb && idx < ib);    // mine precedes (desc)
            bool sw = (up == lowerLane) ? !pre : pre;
            if (sw) { v = vb; idx = ib; }
        }
    }

    // k = 64..512: smem phases for j>=32, then shfl for j<=16
    for (int k = 64; k <= 512; k <<= 1) {
        sv[tid] = v; si[tid] = idx;
        __syncthreads();
        for (int j = k >> 1; j >= 32; j >>= 1) {
            int ixj = tid ^ j;
            if (ixj > tid) {
                float va = sv[tid], vb2 = sv[ixj];
                int   ia = si[tid], ib2 = si[ixj];
                bool aFirst = (va > vb2) || (va == vb2 && ia < ib2);
                bool desc = ((tid & k) == 0);
                bool sw = desc ? !aFirst : aFirst;
                if (sw) { sv[tid] = vb2; sv[ixj] = va; si[tid] = ib2; si[ixj] = ia; }
            }
            __syncthreads();
        }
        v = sv[tid]; idx = si[tid];
        bool up = ((tid & k) == 0);
        #pragma unroll
        for (int j = 16; j > 0; j >>= 1) {
            float vb = __shfl_xor_sync(0xffffffffu, v, j);
            int   ib = __shfl_xor_sync(0xffffffffu, idx, j);
            bool lowerLane = ((tid & j) == 0);
            bool pre = (v > vb) || (v == vb && idx < ib);
            bool sw = (up == lowerLane) ? !pre : pre;
            if (sw) { v = vb; idx = ib; }
        }
    }

    if (tid < Kk) {
        g_selidx[b * Kk + tid] = idx;
        g_stanh[b * Kk + tid]  = tanhf(v * s_inv);
    }
}

// ---------------------------------------------------------------------------
// Kernel: gather + BatchNorm -> bf16 xn   grid (64, 16)
// ---------------------------------------------------------------------------
__global__ void k_bn(const float* __restrict__ feat,
                     const float* __restrict__ bn_mean, const float* __restrict__ bn_var,
                     const float* __restrict__ bn_gamma, const float* __restrict__ bn_beta) {
    int b = blockIdx.x, q = blockIdx.y, tid = threadIdx.x;
    const float* xg = feat + (size_t)11 * Nn * Ff + (size_t)b * NPG * Ff;
    int base = q * (LIN / 16);
    for (int t = tid; t < LIN / 16; t += 256) {
        int i = base + t;
        int r = i >> 6, f = i & 63;
        int idx = g_selidx[b * Kk + r];
        float st = g_stanh[b * Kk + r];
        float xv = xg[idx * Ff + f];
        float xn = (xv * st - bn_mean[i]) * rsqrtf(bn_var[i] + BN_EPS) * bn_gamma[i] + bn_beta[i];
        g_xb[(size_t)b * LIN + i] = __float2bfloat16(xn);
    }
}

// ---------------------------------------------------------------------------
// GEMM1 (frozen R12 structure):  hb[s][m][j] = sum_{k chunk s} xn[m,k]*W1[j,k]
// 128 thr (4 warps), warp tile 32m x 64j, BN=128, BK=32, 2-stage smem,
// 4 CTAs/SM. W: LDG fp32 -> bf16 regs -> STS. X: cp.async.
// grid (63, 8) = 504 CTAs, one wave. Last j-block overlaps (benign dup writes).
// Epilogue now writes bf16 partials (halved traffic).
// ---------------------------------------------------------------------------
#define BN1   128
#define BK1   32
#define ROWB  80                    // bytes per smem row (40 halves)
#define W_BYTES (128 * ROWB)        // 10240
#define X_BYTES (64 * ROWB)         // 5120
#define STG_B   (W_BYTES + X_BYTES) // 15360

__device__ __forceinline__ void mma16816(float* d,
                                         unsigned a0, unsigned a1, unsigned a2, unsigned a3,
                                         unsigned b0, unsigned b1) {
    asm volatile(
        "mma.sync.aligned.m16n8k16.row.col.f32.bf16.bf16.f32 "
        "{%0,%1,%2,%3}, {%4,%5,%6,%7}, {%8,%9}, {%0,%1,%2,%3};\n"
        : "+f"(d[0]), "+f"(d[1]), "+f"(d[2]), "+f"(d[3])
        : "r"(a0), "r"(a1), "r"(a2), "r"(a3), "r"(b0), "r"(b1));
}

__device__ __forceinline__ void ldsm4(unsigned& r0, unsigned& r1, unsigned& r2, unsigned& r3,
                                      unsigned addr) {
    asm volatile("ldmatrix.sync.aligned.m8n8.x4.shared.b16 {%0,%1,%2,%3}, [%4];"
                 : "=r"(r0), "=r"(r1), "=r"(r2), "=r"(r3) : "r"(addr));
}

__device__ __forceinline__ void cpa16(unsigned dst, const void* src) {
    asm volatile("cp.async.cg.shared.global [%0], [%1], 16;" :: "r"(dst), "l"(src));
}

__global__ __launch_bounds__(128, 4) void k_gemm1(const float* __restrict__ W1) {
    __shared__ __align__(16) unsigned char sm[2 * STG_B];
    unsigned smbase = (unsigned)__cvta_generic_to_shared(sm);

    int tid  = threadIdx.x;
    int warp = tid >> 5, lane = tid & 31;
    int wm = warp >> 1, wj = warp & 1;          // 2x2 warp grid
    int gi = lane >> 2, qi = lane & 3;
    int jbase = blockIdx.x * BN1;
    if (jbase > Hh - BN1) jbase = Hh - BN1;     // overlap last block (dup writes benign)
    int kbase = blockIdx.y * 2048;
    int iters = (blockIdx.y == KSPLIT - 1) ? 52 : 64;  // 52*32=1664, 64*32=2048

    // W mapping: 8 float4/thread. chunk c = tid + i*128: row = (tid>>3)+i*16, c8 = tid&7
    int wrow0 = tid >> 3, wc8 = tid & 7;
    const float* wbase = W1 + (size_t)(jbase + wrow0) * LIN + kbase + wc8 * 4;
    unsigned wdst0 = smbase + (unsigned)(wrow0 * ROWB + wc8 * 8);

    // X mapping (cp.async): 2 chunks/thread. row = (tid>>2)+i*32, seg = tid&3
    int xrow0 = tid >> 2, xseg = tid & 3;
    const __nv_bfloat16* xbase = g_xb + (size_t)xrow0 * LIN + kbase + xseg * 8;
    unsigned xdst0 = smbase + (unsigned)(W_BYTES + xrow0 * ROWB + xseg * 16);

    // ldmatrix per-lane offsets (row stride 80B; conflict-free)
    unsigned offA = (unsigned)((lane & 15) * ROWB + (lane >> 4) * 16);
    unsigned offB = (unsigned)((((lane >> 4) & 1) * 8 + (lane & 7)) * ROWB + ((lane >> 3) & 1) * 16);
    unsigned aAddr0 = smbase + W_BYTES + (wm * 32) * ROWB + offA;       // mt=0
    unsigned aAddr1 = aAddr0 + 16 * ROWB;                                // mt=1
    unsigned bAddrB = smbase + (wj * 64) * ROWB + offB;                  // nt pairs at +p*16*ROWB

    float acc[2][8][4];
    #pragma unroll
    for (int a = 0; a < 2; a++)
        #pragma unroll
        for (int b = 0; b < 8; b++)
            #pragma unroll
            for (int q = 0; q < 4; q++) acc[a][b][q] = 0.f;

    // prologue: X stage 0 via cp.async; W iter 0 into registers
    #pragma unroll
    for (int i = 0; i < 2; i++)
        cpa16(xdst0 + i * (32 * ROWB), xbase + (size_t)i * 32 * LIN);
    asm volatile("cp.async.commit_group;");
    float4 wv[8];
    #pragma unroll
    for (int i = 0; i < 8; i++)
        wv[i] = *(const float4*)(wbase + (size_t)i * 16 * LIN);

    #pragma unroll 2
    for (int it = 0; it < iters; it++) {
        unsigned st = (unsigned)(it & 1) * STG_B;
        unsigned sn = (unsigned)((it + 1) & 1) * STG_B;

        // STS: convert W to bf16 (8B per chunk)
        #pragma unroll
        for (int i = 0; i < 8; i++) {
            __nv_bfloat162 p0 = __floats2bfloat162_rn(wv[i].x, wv[i].y);
            __nv_bfloat162 p1 = __floats2bfloat162_rn(wv[i].z, wv[i].w);
            asm volatile("st.shared.v2.b32 [%0], {%1,%2};"
                         :: "r"(wdst0 + st + (unsigned)(i * 16 * ROWB)),
                            "r"(*(unsigned*)&p0), "r"(*(unsigned*)&p1));
        }

        // issue next-iter loads (X cp.async into other stage; W LDG into regs)
        if (it + 1 < iters) {
            int ko = (it + 1) * BK1;
            #pragma unroll
            for (int i = 0; i < 2; i++)
                cpa16(xdst0 + sn + i * (32 * ROWB), xbase + (size_t)i * 32 * LIN + ko);
            #pragma unroll
            for (int i = 0; i < 8; i++)
                wv[i] = *(const float4*)(wbase + (size_t)i * 16 * LIN + ko);
        }
        asm volatile("cp.async.commit_group;");
        asm volatile("cp.async.wait_group 1;");   // current iter's X group done
        __syncthreads();

        // two k16 sub-chunks: per warp 6 LDSM + 16 MMA each
        #pragma unroll
        for (int kk = 0; kk < 2; kk++) {
            unsigned ko = st + (unsigned)(kk * 32);   // 16 halves = 32B
            unsigned a0[2], a1[2], a2[2], a3[2];
            ldsm4(a0[0], a1[0], a2[0], a3[0], aAddr0 + ko);
            ldsm4(a0[1], a1[1], a2[1], a3[1], aAddr1 + ko);
            #pragma unroll
            for (int p = 0; p < 4; p++) {            // n-tile pairs
                unsigned b00, b01, b10, b11;
                ldsm4(b00, b01, b10, b11, bAddrB + ko + (unsigned)(p * 16 * ROWB));
                #pragma unroll
                for (int mt = 0; mt < 2; mt++) {
                    mma16816(acc[mt][p * 2],     a0[mt], a1[mt], a2[mt], a3[mt], b00, b01);
                    mma16816(acc[mt][p * 2 + 1], a0[mt], a1[mt], a2[mt], a3[mt], b10, b11);
                }
            }
        }
        __syncthreads();
    }

    // epilogue: bf16x2 STG into split-private partials (no guard; overlap benign)
    __nv_bfloat16* hp = &g_hb[blockIdx.y][0][0];
    #pragma unroll
    for (int mt = 0; mt < 2; mt++) {
        #pragma unroll
        for (int nt = 0; nt < 8; nt++) {
            int m = wm * 32 + mt * 16 + gi;
            int j = jbase + wj * 64 + nt * 8 + qi * 2;
            __nv_bfloat162 p0 = __floats2bfloat162_rn(acc[mt][nt][0], acc[mt][nt][1]);
            __nv_bfloat162 p1 = __floats2bfloat162_rn(acc[mt][nt][2], acc[mt][nt][3]);
            *(unsigned*)(hp + (size_t)m * Hh + j)       = *(unsigned*)&p0;
            *(unsigned*)(hp + (size_t)(m + 8) * Hh + j) = *(unsigned*)&p1;
        }
    }
}

// ---------------------------------------------------------------------------
// GEMM2 + split-reduce + bias + relu + hierarchical-atomic loss.
// grid (64, 8), 256 thr. Block (m,q): j in [q*1000, q*1000+1000), 4 j/thread.
// Tree: block -> g_lm[m] (8 arrivals) -> per-m last: softplus -> g_loss
// (64 arrivals) -> global last writes out. All counters self-reset.
// ---------------------------------------------------------------------------
__global__ void k_gemm2(const float* __restrict__ b1, const float* __restrict__ W2,
                        const float* __restrict__ b2, float* __restrict__ out) {
    int m = blockIdx.x, q = blockIdx.y, tid = threadIdx.x;
    float s = 0.f;
    if (tid < 250) {                          // 250 threads x 4 j = 1000 j
        int j = q * (Hh / G2SPLIT) + tid * 4;
        float h0 = 0.f, h1 = 0.f, h2 = 0.f, h3 = 0.f;
        #pragma unroll
        for (int sp = 0; sp < KSPLIT; sp++) {
            uint2 hv = *(const uint2*)(&g_hb[sp][m][j]);
            __nv_bfloat162 p0 = *(__nv_bfloat162*)&hv.x;
            __nv_bfloat162 p1 = *(__nv_bfloat162*)&hv.y;
            h0 += __bfloat162float(p0.x); h1 += __bfloat162float(p0.y);
            h2 += __bfloat162float(p1.x); h3 += __bfloat162float(p1.y);
        }
        float4 bv = *(const float4*)(b1 + j);
        float4 wv = *(const float4*)(W2 + j);
        s += fmaxf(h0 + bv.x, 0.f) * wv.x;
        s += fmaxf(h1 + bv.y, 0.f) * wv.y;
        s += fmaxf(h2 + bv.z, 0.f) * wv.z;
        s += fmaxf(h3 + bv.w, 0.f) * wv.w;
    }
    #pragma unroll
    for (int o = 16; o > 0; o >>= 1) s += __shfl_down_sync(0xffffffffu, s, o);
    __shared__ float red[8];
    if ((tid & 31) == 0) red[tid >> 5] = s;
    __syncthreads();

    if (tid == 0) {
        float tot = 0.f;
        #pragma unroll
        for (int i = 0; i < 8; i++) tot += red[i];
        atomicAdd(&g_lm[m], tot);
        __threadfence();
        int old = atomicAdd(&g_cntm[m], 1);
        if (old == G2SPLIT - 1) {
            // last block of this m: all adds to g_lm[m] visible
            float l = atomicAdd(&g_lm[m], 0.f) + b2[0];
            float per = (l > 0.f) ? log1pf(expf(-l)) : (log1pf(expf(l)) - l);
            atomicAdd(&g_loss, per);
            __threadfence();
            int o2 = atomicAdd(&g_done, 1);
            if (o2 == Bb - 1) {
                out[0] = atomicAdd(&g_loss, 0.f) * (1.0f / Bb);
                g_loss = 0.f;               // reset for next graph replay
                g_done = 0;
            }
            g_lm[m] = 0.f;                  // self-reset
            g_cntm[m] = 0;
        }
    }
}

// ---------------------------------------------------------------------------
extern "C" void kernel_launch(void* const* d_in, const int* in_sizes, int n_in,
                              void* d_out, int out_size) {
    const float* feat     = (const float*)d_in[0];
    const float* w        = (const float*)d_in[3];
    const float* bn_gamma = (const float*)d_in[4];
    const float* bn_beta  = (const float*)d_in[5];
    const float* bn_mean  = (const float*)d_in[6];
    const float* bn_var   = (const float*)d_in[7];
    const float* W1       = (const float*)d_in[8];
    const float* b1       = (const float*)d_in[9];
    const float* W2       = (const float*)d_in[10];
    const float* b2       = (const float*)d_in[11];

    k_sort<<<Bb, 512>>>(feat, w);
    dim3 gbn(Bb, 16);
    k_bn<<<gbn, 256>>>(feat, bn_mean, bn_var, bn_gamma, bn_beta);
    dim3 g1(63, KSPLIT);   // 504 CTAs, 4/SM -> one wave
    k_gemm1<<<g1, 128>>>(W1);
    dim3 g2(Bb, G2SPLIT);
    k_gemm2<<<g2, 256>>>(b1, W2, b2, (float*)d_out);
}